// round 15
// baseline (speedup 1.0000x reference)
#include <cuda_runtime.h>
#include <cuda_fp16.h>
#include <cstdint>

// Problem constants
#define BSZ 8
#define SEQT 256
#define NJ 24
#define DIM 512
#define NH 8
#define HD 64

#define QKV_ELEMS (BSZ * NJ * SEQT * DIM)  // 25,165,824
#define W_ELEMS   (NJ * DIM * DIM)         // 6,291,456

// fp16 operands / intermediates
__device__ __half g_Xh[QKV_ELEMS];       // x, layout [b][t][j][d]
__device__ __half g_Whq[W_ELEMS];        // W transposed: [j][n][k]
__device__ __half g_Whk[W_ELEMS];
__device__ __half g_Whv[W_ELEMS];
__device__ __half g_Woh[DIM * DIM];      // Wo [n][k]
__device__ __half g_Qh[QKV_ELEMS];       // Q pre-scaled by 0.125, [b][j][t][e]
__device__ __half g_Kh[QKV_ELEMS];       // K, [b][j][t][e]
__device__ __half g_Vth[QKV_ELEMS];      // V transposed, [b][j][e][t]
__device__ __half g_Oh[QKV_ELEMS];       // attention out, [b][j][t][e]

__device__ __forceinline__ uint32_t pkh2(float x, float y) {
    __half2 h = __float22half2_rn(make_float2(x, y));
    return *(uint32_t*)&h;
}

__device__ __forceinline__ void mma_f16(
    float& c0, float& c1, float& c2, float& c3,
    uint32_t a0, uint32_t a1, uint32_t a2, uint32_t a3,
    uint32_t b0, uint32_t b1)
{
    asm volatile(
        "mma.sync.aligned.m16n8k16.row.col.f32.f16.f16.f32 "
        "{%0,%1,%2,%3}, {%4,%5,%6,%7}, {%8,%9}, {%0,%1,%2,%3};\n"
        : "+f"(c0), "+f"(c1), "+f"(c2), "+f"(c3)
        : "r"(a0), "r"(a1), "r"(a2), "r"(a3), "r"(b0), "r"(b1));
}

__device__ __forceinline__ void ldsm4(uint32_t& r0, uint32_t& r1,
                                      uint32_t& r2, uint32_t& r3, uint32_t addr)
{
    asm volatile("ldmatrix.sync.aligned.m8n8.x4.shared.b16 {%0,%1,%2,%3}, [%4];"
                 : "=r"(r0), "=r"(r1), "=r"(r2), "=r"(r3) : "r"(addr));
}

__device__ __forceinline__ void cpasync16(uint32_t dst, const void* src) {
    asm volatile("cp.async.cg.shared.global [%0], [%1], 16;\n"
                 :: "r"(dst), "l"(src));
}
#define CP_COMMIT() asm volatile("cp.async.commit_group;\n" ::: "memory")
#define CP_WAIT(N)  asm volatile("cp.async.wait_group %0;\n" :: "n"(N) : "memory")

// ---------------------------------------------------------------------------
// Fused pre-pass (R14-verbatim)
// ---------------------------------------------------------------------------
#define XB   (QKV_ELEMS / 4 / 256)           // 24576
#define WTB  (16 * 16 * 72)                  // 18432
#define WOB  (DIM * DIM / 4 / 256)           // 256

__global__ __launch_bounds__(256)
void cvt_fused_kernel(const float4* __restrict__ x,
                      const float* __restrict__ Wq,
                      const float* __restrict__ Wk,
                      const float* __restrict__ Wv,
                      const float4* __restrict__ Wo)
{
    __shared__ float tile[32][33];
    const int bid = blockIdx.x;
    const int tid = threadIdx.x;

    if (bid < XB) {
        int i = bid * 256 + tid;
        float4 v = x[i];
        ((uint2*)g_Xh)[i] = make_uint2(pkh2(v.x, v.y), pkh2(v.z, v.w));
    } else if (bid < XB + WTB) {
        int r = bid - XB;
        int bx = r & 15;
        int by = (r >> 4) & 15;
        int z  = r >> 8;
        int j  = z % NJ;
        int p  = z / NJ;
        const float* W = (p == 0) ? Wq : ((p == 1) ? Wk : Wv);
        __half* Wh     = (p == 0) ? g_Whq : ((p == 1) ? g_Whk : g_Whv);
        int n0 = bx * 32, k0 = by * 32;
        int tx = tid & 31, ty = tid >> 5;
        const size_t base = (size_t)j * DIM * DIM;
#pragma unroll
        for (int i = 0; i < 4; i++)
            tile[ty + 8 * i][tx] = W[base + (size_t)(k0 + ty + 8 * i) * DIM + n0 + tx];
        __syncthreads();
#pragma unroll
        for (int i = 0; i < 4; i++)
            Wh[base + (size_t)(n0 + ty + 8 * i) * DIM + k0 + tx] =
                __float2half(tile[tx][ty + 8 * i]);
    } else {
        int i = (bid - XB - WTB) * 256 + tid;
        float4 v = Wo[i];
        ((uint2*)g_Woh)[i] = make_uint2(pkh2(v.x, v.y), pkh2(v.z, v.w));
    }
}

// ---------------------------------------------------------------------------
// Kernel 1: per-joint Q/K/V projection. Block tile 128x256 (BN=256 halves
// A-traffic), BK=32, 512 threads = 16 warps (2M x 8N, warp 64x32 = identical
// per-warp hot loop to R11/R14). 3-stage cp.async ring + ldmatrix.
// grid: (2, 16, 72). smem V-transpose epilogue (coalesced Vt stores).
// ---------------------------------------------------------------------------
#define QSAU 20
#define QA_U   (128 * QSAU)                 // 2560 u32 (A)
#define QB_U   (256 * QSAU)                 // 5120 u32 (B)
#define QSTG_U (QA_U + QB_U)                // 7680 u32 = 30720 B per stage
#define QKV_SMEM (3 * QSTG_U * 4)           // 92160 B
#define TST 136                             // half-stride for [e][t] transpose rows

__global__ __launch_bounds__(512, 1)
void qkv_tc_kernel()
{
    extern __shared__ uint32_t smem[];
    const uint32_t sbase = (uint32_t)__cvta_generic_to_shared(smem);

    const int nt = blockIdx.x;   // 0..1 (N/256)
    const int mt = blockIdx.y;   // 0..15
    const int z  = blockIdx.z;
    const int j  = z % NJ;
    const int p  = z / NJ;

    const __half* Wh = (p == 0) ? g_Whq : ((p == 1) ? g_Whk : g_Whv);

    const int tid  = threadIdx.x;
    const int wid  = tid >> 5;
    const int lane = tid & 31;
    const int wm   = (wid >> 3) * 64;    // 0 or 64
    const int wn   = (wid & 7) * 32;     // 0..224
    const int grp  = lane >> 2;
    const int qd   = lane & 3;

    const int a_row = (lane & 15);
    const int a_k   = 4 * (lane >> 4);
    const int b_n   = (lane & 7) + 8 * (lane >> 4);
    const int b_k   = 4 * ((lane >> 3) & 1);

    const size_t wbase = (size_t)j * DIM * DIM + (size_t)nt * 256 * DIM;

    float acc[4][4][4];
#pragma unroll
    for (int i = 0; i < 4; i++)
#pragma unroll
        for (int jn = 0; jn < 4; jn++)
#pragma unroll
            for (int c = 0; c < 4; c++)
                acc[i][jn][c] = 0.0f;

    auto stage = [&](int kb, int bf) {
        uint32_t ab = sbase + bf * (QSTG_U * 4);
        uint32_t bb = ab + QA_U * 4;
        // A: 512 float4 tasks (128 rows x 4)
        {
            int row = tid >> 2;
            int cc  = tid & 3;
            cpasync16(ab + row * (QSAU * 4) + cc * 16,
                      g_Xh + ((size_t)(mt * 128 + row) * NJ + j) * DIM + kb * 32 + cc * 8);
        }
        // B: 1024 float4 tasks (256 rows x 4)
#pragma unroll
        for (int l = 0; l < 2; l++) {
            int c   = tid + l * 512;
            int row = c >> 2;
            int cc  = c & 3;
            cpasync16(bb + row * (QSAU * 4) + cc * 16,
                      Wh + wbase + (size_t)row * DIM + kb * 32 + cc * 8);
        }
    };

    stage(0, 0);
    CP_COMMIT();
    stage(1, 1);
    CP_COMMIT();

    const int NKB = DIM / 32;   // 16
    for (int kb = 0; kb < NKB; kb++) {
        if (kb < NKB - 1) { CP_WAIT(1); } else { CP_WAIT(0); }
        __syncthreads();
        if (kb + 2 < NKB) {
            stage(kb + 2, (kb + 2) % 3);
            CP_COMMIT();
        }

        const uint32_t abase = sbase + (kb % 3) * (QSTG_U * 4);
        const uint32_t bbase = abase + QA_U * 4;

#pragma unroll
        for (int kk = 0; kk < 2; kk++) {
            const int kp = kk * 8;
            uint32_t a[4][4];
#pragma unroll
            for (int i = 0; i < 4; i++) {
                uint32_t addr = abase +
                    ((wm + 16 * i + a_row) * QSAU + kp + a_k) * 4;
                ldsm4(a[i][0], a[i][1], a[i][2], a[i][3], addr);
            }
            uint32_t b[4][2];
#pragma unroll
            for (int jp = 0; jp < 2; jp++) {
                uint32_t addr = bbase +
                    ((wn + 16 * jp + b_n) * QSAU + kp + b_k) * 4;
                ldsm4(b[2 * jp][0], b[2 * jp][1], b[2 * jp + 1][0], b[2 * jp + 1][1], addr);
            }
#pragma unroll
            for (int i = 0; i < 4; i++)
#pragma unroll
                for (int jn = 0; jn < 4; jn++)
                    mma_f16(acc[i][jn][0], acc[i][jn][1], acc[i][jn][2], acc[i][jn][3],
                            a[i][0], a[i][1], a[i][2], a[i][3],
                            b[jn][0], b[jn][1]);
        }
    }

    // Epilogue
    if (p < 2) {
        __half* outh = (p == 0) ? g_Qh : g_Kh;
        const float scl = (p == 0) ? 0.125f : 1.0f;
#pragma unroll
        for (int i = 0; i < 4; i++) {
            int m = mt * 128 + wm + 16 * i + grp;
            int b = m >> 8;
            int t = m & (SEQT - 1);
            size_t r0 = (((size_t)(b * NJ + j) * SEQT) + t) * DIM + nt * 256 + wn;
            size_t r1 = r0 + (size_t)8 * DIM;
#pragma unroll
            for (int jn = 0; jn < 4; jn++) {
                int col = 8 * jn + 2 * qd;
                *(uint32_t*)&outh[r0 + col] = pkh2(acc[i][jn][0] * scl, acc[i][jn][1] * scl);
                *(uint32_t*)&outh[r1 + col] = pkh2(acc[i][jn][2] * scl, acc[i][jn][3] * scl);
            }
        }
    } else {
        // V: transpose through smem, then coalesced 16B stores of Vt rows.
        __syncthreads();
        __half* smT = (__half*)smem;           // [256 e][TST t] = 69632 B
#pragma unroll
        for (int i = 0; i < 4; i++) {
            int tl0 = wm + 16 * i + grp;       // local t 0..127
            int tl1 = tl0 + 8;
#pragma unroll
            for (int jn = 0; jn < 4; jn++) {
                int e0 = wn + 8 * jn + 2 * qd; // local e 0..255
                smT[e0 * TST + tl0]       = __float2half(acc[i][jn][0]);
                smT[(e0 + 1) * TST + tl0] = __float2half(acc[i][jn][1]);
                smT[e0 * TST + tl1]       = __float2half(acc[i][jn][2]);
                smT[(e0 + 1) * TST + tl1] = __float2half(acc[i][jn][3]);
            }
        }
        __syncthreads();
        // 256 e-rows x 128 t halves = 4096 uint4
        const int b  = (mt * 128) >> 8;
        const int t0 = (mt * 128) & (SEQT - 1);
        const size_t gb = ((size_t)(b * NJ + j) * DIM + nt * 256) * SEQT + t0;
#pragma unroll
        for (int l = 0; l < 8; l++) {
            int idx = tid + l * 512;
            int e   = idx >> 4;
            int q4  = idx & 15;
            uint4 v = *(uint4*)&smT[e * TST + q4 * 8];
            *(uint4*)&g_Vth[gb + (size_t)e * SEQT + q4 * 8] = v;
        }
    }
}

// ---------------------------------------------------------------------------
// Kernel 2: fp16 flash attention with ldmatrix (R14-verbatim).
// ---------------------------------------------------------------------------
#define AQ_ST 36
#define AV_ST 132
#define ATT_U (2 * SEQT * AQ_ST + HD * AV_ST)
#define ATT_SMEM (ATT_U * 4)

__global__ __launch_bounds__(512)
void attn_tc_kernel()
{
    extern __shared__ uint32_t smu[];
    const uint32_t sbase = (uint32_t)__cvta_generic_to_shared(smu);
    const uint32_t qs_b = sbase;
    const uint32_t ks_b = sbase + SEQT * AQ_ST * 4;
    const uint32_t vt_b = sbase + 2 * SEQT * AQ_ST * 4;

    const int bjh = blockIdx.x;
    const int h   = bjh & (NH - 1);
    const int bj  = bjh >> 3;
    const int tid  = threadIdx.x;
    const int wid  = tid >> 5;
    const int lane = tid & 31;
    const int grp  = lane >> 2;
    const int qd   = lane & 3;
    const int m0   = wid * 16;

    const int a_row = (lane & 15);
    const int a_k   = 4 * (lane >> 4);
    const int b_n   = (lane & 7) + 8 * (lane >> 4);
    const int b_k   = 4 * ((lane >> 3) & 1);

    const __half* qg = g_Qh + (size_t)bj * SEQT * DIM + h * HD;
    const __half* kg = g_Kh + (size_t)bj * SEQT * DIM + h * HD;
    const __half* vg = g_Vth + (size_t)bj * DIM * SEQT + (size_t)h * HD * SEQT;

#pragma unroll
    for (int l = 0; l < 4; l++) {
        int idx = tid + l * 512;
        int row = idx >> 3;
        int q4  = idx & 7;
        cpasync16(qs_b + (row * AQ_ST + q4 * 4) * 4, qg + (size_t)row * DIM + q4 * 8);
        cpasync16(ks_b + (row * AQ_ST + q4 * 4) * 4, kg + (size_t)row * DIM + q4 * 8);
    }
#pragma unroll
    for (int l = 0; l < 4; l++) {
        int idx = tid + l * 512;
        int d  = idx >> 5;
        int q4 = idx & 31;
        cpasync16(vt_b + (d * AV_ST + q4 * 4) * 4, vg + (size_t)d * SEQT + q4 * 8);
    }
    CP_COMMIT();
    CP_WAIT(0);
    __syncthreads();

    float oacc[8][4];
#pragma unroll
    for (int jn = 0; jn < 8; jn++)
#pragma unroll
        for (int c = 0; c < 4; c++) oacc[jn][c] = 0.0f;
    float mrow[2] = { -1e30f, -1e30f };
    float lrow[2] = { 0.0f, 0.0f };

    for (int ch = 0; ch < 4; ch++) {
        float sacc[8][4];
#pragma unroll
        for (int jn = 0; jn < 8; jn++)
#pragma unroll
            for (int c = 0; c < 4; c++) sacc[jn][c] = 0.0f;

#pragma unroll
        for (int kt = 0; kt < 4; kt++) {
            const int kp = kt * 8;
            uint32_t a0, a1, a2, a3;
            ldsm4(a0, a1, a2, a3,
                  qs_b + ((m0 + a_row) * AQ_ST + kp + a_k) * 4);
#pragma unroll
            for (int jp = 0; jp < 4; jp++) {
                uint32_t b00, b01, b10, b11;
                ldsm4(b00, b01, b10, b11,
                      ks_b + ((ch * 64 + 16 * jp + b_n) * AQ_ST + kp + b_k) * 4);
                mma_f16(sacc[2 * jp][0], sacc[2 * jp][1], sacc[2 * jp][2], sacc[2 * jp][3],
                        a0, a1, a2, a3, b00, b01);
                mma_f16(sacc[2 * jp + 1][0], sacc[2 * jp + 1][1],
                        sacc[2 * jp + 1][2], sacc[2 * jp + 1][3],
                        a0, a1, a2, a3, b10, b11);
            }
        }

#pragma unroll
        for (int r = 0; r < 2; r++) {
            float mx = -1e30f;
#pragma unroll
            for (int jn = 0; jn < 8; jn++) {
                mx = fmaxf(mx, sacc[jn][2 * r]);
                mx = fmaxf(mx, sacc[jn][2 * r + 1]);
            }
            mx = fmaxf(mx, __shfl_xor_sync(0xffffffffu, mx, 1));
            mx = fmaxf(mx, __shfl_xor_sync(0xffffffffu, mx, 2));
            float mnew = fmaxf(mrow[r], mx);
            float scale = __expf(mrow[r] - mnew);
            mrow[r] = mnew;
            float ps = 0.0f;
#pragma unroll
            for (int jn = 0; jn < 8; jn++) {
                float p0 = __expf(sacc[jn][2 * r] - mnew);
                float p1 = __expf(sacc[jn][2 * r + 1] - mnew);
                sacc[jn][2 * r] = p0;
                sacc[jn][2 * r + 1] = p1;
                ps += p0 + p1;
                oacc[jn][2 * r] *= scale;
                oacc[jn][2 * r + 1] *= scale;
            }
            lrow[r] = lrow[r] * scale + ps;
        }

#pragma unroll
        for (int kt = 0; kt < 4; kt++) {
            uint32_t a0 = pkh2(sacc[2 * kt][0], sacc[2 * kt][1]);
            uint32_t a1 = pkh2(sacc[2 * kt][2], sacc[2 * kt][3]);
            uint32_t a2 = pkh2(sacc[2 * kt + 1][0], sacc[2 * kt + 1][1]);
            uint32_t a3 = pkh2(sacc[2 * kt + 1][2], sacc[2 * kt + 1][3]);
            const int kp = ch * 32 + kt * 8;
#pragma unroll
            for (int jp = 0; jp < 4; jp++) {
                uint32_t b00, b01, b10, b11;
                ldsm4(b00, b01, b10, b11,
                      vt_b + ((16 * jp + b_n) * AV_ST + kp + b_k) * 4);
                mma_f16(oacc[2 * jp][0], oacc[2 * jp][1], oacc[2 * jp][2], oacc[2 * jp][3],
                        a0, a1, a2, a3, b00, b01);
                mma_f16(oacc[2 * jp + 1][0], oacc[2 * jp + 1][1],
                        oacc[2 * jp + 1][2], oacc[2 * jp + 1][3],
                        a0, a1, a2, a3, b10, b11);
            }
        }
    }

    float inv[2];
#pragma unroll
    for (int r = 0; r < 2; r++) {
        float lr = lrow[r];
        lr += __shfl_xor_sync(0xffffffffu, lr, 1);
        lr += __shfl_xor_sync(0xffffffffu, lr, 2);
        inv[r] = 1.0f / lr;
    }
    const size_t obase = (size_t)bj * SEQT * DIM + h * HD;
    __half* o0 = g_Oh + obase + (size_t)(m0 + grp) * DIM;
    __half* o1 = g_Oh + obase + (size_t)(m0 + grp + 8) * DIM;
#pragma unroll
    for (int jn = 0; jn < 8; jn++) {
        int col = 8 * jn + 2 * qd;
        *(uint32_t*)&o0[col] = pkh2(oacc[jn][0] * inv[0], oacc[jn][1] * inv[0]);
        *(uint32_t*)&o1[col] = pkh2(oacc[jn][2] * inv[1], oacc[jn][3] * inv[1]);
    }
}

// ---------------------------------------------------------------------------
// Kernel 3: output projection + bias, BK=64, 3-stage ring + ldmatrix
// (R14-verbatim).
// ---------------------------------------------------------------------------
#define PSAU 36
#define PABUF_U (128 * PSAU)
#define PSTG_U  (2 * PABUF_U)
#define PROJ_SMEM (3 * PSTG_U * 4)

__global__ __launch_bounds__(256, 2)
void proj_tc_kernel(const float* __restrict__ bo,
                    float* __restrict__ out)
{
    extern __shared__ uint32_t smem[];
    const uint32_t sbase = (uint32_t)__cvta_generic_to_shared(smem);

    const int nt = blockIdx.x;
    const int mt = blockIdx.y;

    const int tid  = threadIdx.x;
    const int wid  = tid >> 5;
    const int lane = tid & 31;
    const int wm   = (wid >> 2) * 64;
    const int wn   = (wid & 3) * 32;
    const int grp  = lane >> 2;
    const int qd   = lane & 3;

    const int a_row = (lane & 15);
    const int a_k   = 4 * (lane >> 4);
    const int b_n   = (lane & 7) + 8 * (lane >> 4);
    const int b_k   = 4 * ((lane >> 3) & 1);

    float acc[4][4][4];
#pragma unroll
    for (int i = 0; i < 4; i++)
#pragma unroll
        for (int jn = 0; jn < 4; jn++)
#pragma unroll
            for (int c = 0; c < 4; c++)
                acc[i][jn][c] = 0.0f;

    auto stage = [&](int kb, int bf) {
        uint32_t ab = sbase + bf * (PSTG_U * 4);
        uint32_t bb = ab + PABUF_U * 4;
#pragma unroll
        for (int l = 0; l < 4; l++) {
            int c   = tid + l * 256;
            int row = c >> 3;
            int cc  = c & 7;
            cpasync16(ab + row * (PSAU * 4) + cc * 16,
                      g_Oh + (size_t)(mt * 128 + row) * DIM + kb * 64 + cc * 8);
            cpasync16(bb + row * (PSAU * 4) + cc * 16,
                      g_Woh + (size_t)(nt * 128 + row) * DIM + kb * 64 + cc * 8);
        }
    };

    stage(0, 0);
    CP_COMMIT();
    stage(1, 1);
    CP_COMMIT();

    const int NKB = DIM / 64;
    for (int kb = 0; kb < NKB; kb++) {
        if (kb < NKB - 1) { CP_WAIT(1); } else { CP_WAIT(0); }
        __syncthreads();
        if (kb + 2 < NKB) {
            stage(kb + 2, (kb + 2) % 3);
            CP_COMMIT();
        }

        const uint32_t abase = sbase + (kb % 3) * (PSTG_U * 4);
        const uint32_t bbase = abase + PABUF_U * 4;

#pragma unroll
        for (int kk = 0; kk < 4; kk++) {
            const int kp = kk * 8;
            uint32_t a[4][4];
#pragma unroll
            for (int i = 0; i < 4; i++) {
                uint32_t addr = abase +
                    ((wm + 16 * i + a_row) * PSAU + kp + a_k) * 4;
                ldsm4(a[i][0], a[i][1], a[i][2], a[i][3], addr);
            }
            uint32_t b[4][2];
#pragma unroll
            for (int jp = 0; jp < 2; jp++) {
                uint32_t addr = bbase +
                    ((wn + 16 * jp + b_n) * PSAU + kp + b_k) * 4;
                ldsm4(b[2 * jp][0], b[2 * jp][1], b[2 * jp + 1][0], b[2 * jp + 1][1], addr);
            }
#pragma unroll
            for (int i = 0; i < 4; i++)
#pragma unroll
                for (int jn = 0; jn < 4; jn++)
                    mma_f16(acc[i][jn][0], acc[i][jn][1], acc[i][jn][2], acc[i][jn][3],
                            a[i][0], a[i][1], a[i][2], a[i][3],
                            b[jn][0], b[jn][1]);
        }
    }

#pragma unroll
    for (int i = 0; i < 4; i++) {
        int r = mt * 128 + wm + 16 * i + grp;
        int b = r / (NJ * SEQT);
        int rem = r - b * (NJ * SEQT);
        int jj = rem >> 8;
        int t  = rem & (SEQT - 1);
        size_t base0 = (((size_t)(b * SEQT + t) * NJ) + jj) * DIM + nt * 128 + wn;
        size_t base1 = base0 + (size_t)8 * NJ * DIM;
#pragma unroll
        for (int jn = 0; jn < 4; jn++) {
            int col = 8 * jn + 2 * qd;
            float2 bb = *(const float2*)(bo + nt * 128 + wn + col);
            *(float2*)&out[base0 + col] = make_float2(acc[i][jn][0] + bb.x,
                                                      acc[i][jn][1] + bb.y);
            *(float2*)&out[base1 + col] = make_float2(acc[i][jn][2] + bb.x,
                                                      acc[i][jn][3] + bb.y);
        }
    }
}

// ---------------------------------------------------------------------------
extern "C" void kernel_launch(void* const* d_in, const int* in_sizes, int n_in,
                              void* d_out, int out_size)
{
    const float* x  = (const float*)d_in[0];
    const float* Wq = (const float*)d_in[1];
    const float* Wk = (const float*)d_in[2];
    const float* Wv = (const float*)d_in[3];
    const float* Wo = (const float*)d_in[4];
    const float* bo = (const float*)d_in[5];
    float* out = (float*)d_out;

    // 0) fused pre-convert (one launch)
    cvt_fused_kernel<<<XB + WTB + WOB, 256>>>(
        (const float4*)x, Wq, Wk, Wv, (const float4*)Wo);

    // 1) QKV projection (128x256 tile, BK=32, 3-stage cp.async + ldmatrix)
    cudaFuncSetAttribute(qkv_tc_kernel,
                         cudaFuncAttributeMaxDynamicSharedMemorySize, QKV_SMEM);
    dim3 g1(DIM / 256, (BSZ * SEQT) / 128, 3 * NJ);   // (2, 16, 72)
    qkv_tc_kernel<<<g1, 512, QKV_SMEM>>>();

    // 2) fp16 flash attention (ldmatrix)
    cudaFuncSetAttribute(attn_tc_kernel,
                         cudaFuncAttributeMaxDynamicSharedMemorySize, ATT_SMEM);
    attn_tc_kernel<<<BSZ * NJ * NH, 512, ATT_SMEM>>>();

    // 3) output projection + bias (BK=64, 3-stage + ldmatrix)
    cudaFuncSetAttribute(proj_tc_kernel,
                         cudaFuncAttributeMaxDynamicSharedMemorySize, PROJ_SMEM);
    dim3 g3(DIM / 128, (BSZ * SEQT * NJ) / 128);      // (4, 48)
    proj_tc_kernel<<<g3, 256, PROJ_SMEM>>>(bo, out);
}

// round 16
// speedup vs baseline: 1.0748x; 1.0748x over previous
#include <cuda_runtime.h>
#include <cuda_fp16.h>
#include <cstdint>

// Problem constants
#define BSZ 8
#define SEQT 256
#define NJ 24
#define DIM 512
#define NH 8
#define HD 64

#define QKV_ELEMS (BSZ * NJ * SEQT * DIM)  // 25,165,824
#define W_ELEMS   (NJ * DIM * DIM)         // 6,291,456

// fp16 operands / intermediates
__device__ __half g_Xh[QKV_ELEMS];       // x, layout [b][t][j][d]
__device__ __half g_Whq[W_ELEMS];        // W transposed: [j][n][k]
__device__ __half g_Whk[W_ELEMS];
__device__ __half g_Whv[W_ELEMS];
__device__ __half g_Woh[DIM * DIM];      // Wo [n][k]
__device__ __half g_Qh[QKV_ELEMS];       // Q pre-scaled by 0.125*log2(e), [b][j][t][e]
__device__ __half g_Kh[QKV_ELEMS];       // K, [b][j][t][e]
__device__ __half g_Vth[QKV_ELEMS];      // V transposed, [b][j][e][t]
__device__ __half g_Oh[QKV_ELEMS];       // attention out, [b][j][t][e]

__device__ __forceinline__ uint32_t pkh2(float x, float y) {
    __half2 h = __float22half2_rn(make_float2(x, y));
    return *(uint32_t*)&h;
}

__device__ __forceinline__ void mma_f16(
    float& c0, float& c1, float& c2, float& c3,
    uint32_t a0, uint32_t a1, uint32_t a2, uint32_t a3,
    uint32_t b0, uint32_t b1)
{
    asm volatile(
        "mma.sync.aligned.m16n8k16.row.col.f32.f16.f16.f32 "
        "{%0,%1,%2,%3}, {%4,%5,%6,%7}, {%8,%9}, {%0,%1,%2,%3};\n"
        : "+f"(c0), "+f"(c1), "+f"(c2), "+f"(c3)
        : "r"(a0), "r"(a1), "r"(a2), "r"(a3), "r"(b0), "r"(b1));
}

__device__ __forceinline__ void ldsm4(uint32_t& r0, uint32_t& r1,
                                      uint32_t& r2, uint32_t& r3, uint32_t addr)
{
    asm volatile("ldmatrix.sync.aligned.m8n8.x4.shared.b16 {%0,%1,%2,%3}, [%4];"
                 : "=r"(r0), "=r"(r1), "=r"(r2), "=r"(r3) : "r"(addr));
}

__device__ __forceinline__ void cpasync16(uint32_t dst, const void* src) {
    asm volatile("cp.async.cg.shared.global [%0], [%1], 16;\n"
                 :: "r"(dst), "l"(src));
}
#define CP_COMMIT() asm volatile("cp.async.commit_group;\n" ::: "memory")
#define CP_WAIT(N)  asm volatile("cp.async.wait_group %0;\n" :: "n"(N) : "memory")

// ---------------------------------------------------------------------------
// Fused pre-pass (R14-verbatim)
// ---------------------------------------------------------------------------
#define XB   (QKV_ELEMS / 4 / 256)           // 24576
#define WTB  (16 * 16 * 72)                  // 18432
#define WOB  (DIM * DIM / 4 / 256)           // 256

__global__ __launch_bounds__(256)
void cvt_fused_kernel(const float4* __restrict__ x,
                      const float* __restrict__ Wq,
                      const float* __restrict__ Wk,
                      const float* __restrict__ Wv,
                      const float4* __restrict__ Wo)
{
    __shared__ float tile[32][33];
    const int bid = blockIdx.x;
    const int tid = threadIdx.x;

    if (bid < XB) {
        int i = bid * 256 + tid;
        float4 v = x[i];
        ((uint2*)g_Xh)[i] = make_uint2(pkh2(v.x, v.y), pkh2(v.z, v.w));
    } else if (bid < XB + WTB) {
        int r = bid - XB;
        int bx = r & 15;
        int by = (r >> 4) & 15;
        int z  = r >> 8;
        int j  = z % NJ;
        int p  = z / NJ;
        const float* W = (p == 0) ? Wq : ((p == 1) ? Wk : Wv);
        __half* Wh     = (p == 0) ? g_Whq : ((p == 1) ? g_Whk : g_Whv);
        int n0 = bx * 32, k0 = by * 32;
        int tx = tid & 31, ty = tid >> 5;
        const size_t base = (size_t)j * DIM * DIM;
#pragma unroll
        for (int i = 0; i < 4; i++)
            tile[ty + 8 * i][tx] = W[base + (size_t)(k0 + ty + 8 * i) * DIM + n0 + tx];
        __syncthreads();
#pragma unroll
        for (int i = 0; i < 4; i++)
            Wh[base + (size_t)(n0 + ty + 8 * i) * DIM + k0 + tx] =
                __float2half(tile[tx][ty + 8 * i]);
    } else {
        int i = (bid - XB - WTB) * 256 + tid;
        float4 v = Wo[i];
        ((uint2*)g_Woh)[i] = make_uint2(pkh2(v.x, v.y), pkh2(v.z, v.w));
    }
}

// ---------------------------------------------------------------------------
// Kernel 1: per-joint Q/K/V projection, fp16 m16n8k16, BK=32, 3-stage
// cp.async ring + ldmatrix, smem V-transpose (R14-verbatim except Q scale
// now folds log2(e) for the exp2 softmax).
// Block 128x128, 256 threads, 2 CTAs/SM. grid: (4, 16, 72)
// ---------------------------------------------------------------------------
#define QSAU 20
#define QABUF_U (128 * QSAU)          // 2560 u32
#define QSTG_U  (2 * QABUF_U)         // 5120 u32 = 20480 B per stage
#define QKV_SMEM (3 * QSTG_U * 4)     // 61440 B
#define TST 136                       // half-stride for [e][t] transpose rows

__global__ __launch_bounds__(256, 2)
void qkv_tc_kernel()
{
    extern __shared__ uint32_t smem[];
    const uint32_t sbase = (uint32_t)__cvta_generic_to_shared(smem);

    const int nt = blockIdx.x;
    const int mt = blockIdx.y;
    const int z  = blockIdx.z;
    const int j  = z % NJ;
    const int p  = z / NJ;

    const __half* Wh = (p == 0) ? g_Whq : ((p == 1) ? g_Whk : g_Whv);

    const int tid  = threadIdx.x;
    const int wid  = tid >> 5;
    const int lane = tid & 31;
    const int wm   = (wid >> 2) * 64;
    const int wn   = (wid & 3) * 32;
    const int grp  = lane >> 2;
    const int qd   = lane & 3;

    const int a_row = (lane & 15);
    const int a_k   = 4 * (lane >> 4);
    const int b_n   = (lane & 7) + 8 * (lane >> 4);
    const int b_k   = 4 * ((lane >> 3) & 1);

    const size_t wbase = (size_t)j * DIM * DIM + (size_t)nt * 128 * DIM;

    float acc[4][4][4];
#pragma unroll
    for (int i = 0; i < 4; i++)
#pragma unroll
        for (int jn = 0; jn < 4; jn++)
#pragma unroll
            for (int c = 0; c < 4; c++)
                acc[i][jn][c] = 0.0f;

    auto stage = [&](int kb, int bf) {
        uint32_t ab = sbase + bf * (QSTG_U * 4);
        uint32_t bb = ab + QABUF_U * 4;
#pragma unroll
        for (int l = 0; l < 2; l++) {
            int c   = tid + l * 256;
            int row = c >> 2;
            int cc  = c & 3;
            cpasync16(ab + row * (QSAU * 4) + cc * 16,
                      g_Xh + ((size_t)(mt * 128 + row) * NJ + j) * DIM + kb * 32 + cc * 8);
            cpasync16(bb + row * (QSAU * 4) + cc * 16,
                      Wh + wbase + (size_t)row * DIM + kb * 32 + cc * 8);
        }
    };

    stage(0, 0);
    CP_COMMIT();
    stage(1, 1);
    CP_COMMIT();

    const int NKB = DIM / 32;   // 16
    for (int kb = 0; kb < NKB; kb++) {
        if (kb < NKB - 1) { CP_WAIT(1); } else { CP_WAIT(0); }
        __syncthreads();
        if (kb + 2 < NKB) {
            stage(kb + 2, (kb + 2) % 3);
            CP_COMMIT();
        }

        const uint32_t abase = sbase + (kb % 3) * (QSTG_U * 4);
        const uint32_t bbase = abase + QABUF_U * 4;

#pragma unroll
        for (int kk = 0; kk < 2; kk++) {
            const int kp = kk * 8;
            uint32_t a[4][4];
#pragma unroll
            for (int i = 0; i < 4; i++) {
                uint32_t addr = abase +
                    ((wm + 16 * i + a_row) * QSAU + kp + a_k) * 4;
                ldsm4(a[i][0], a[i][1], a[i][2], a[i][3], addr);
            }
            uint32_t b[4][2];
#pragma unroll
            for (int jp = 0; jp < 2; jp++) {
                uint32_t addr = bbase +
                    ((wn + 16 * jp + b_n) * QSAU + kp + b_k) * 4;
                ldsm4(b[2 * jp][0], b[2 * jp][1], b[2 * jp + 1][0], b[2 * jp + 1][1], addr);
            }
#pragma unroll
            for (int i = 0; i < 4; i++)
#pragma unroll
                for (int jn = 0; jn < 4; jn++)
                    mma_f16(acc[i][jn][0], acc[i][jn][1], acc[i][jn][2], acc[i][jn][3],
                            a[i][0], a[i][1], a[i][2], a[i][3],
                            b[jn][0], b[jn][1]);
        }
    }

    // Epilogue
    if (p < 2) {
        __half* outh = (p == 0) ? g_Qh : g_Kh;
        // Q carries hd^-0.5 * log2(e) so attention can use exp2
        const float scl = (p == 0) ? (0.125f * 1.44269504f) : 1.0f;
#pragma unroll
        for (int i = 0; i < 4; i++) {
            int m = mt * 128 + wm + 16 * i + grp;
            int b = m >> 8;
            int t = m & (SEQT - 1);
            size_t r0 = (((size_t)(b * NJ + j) * SEQT) + t) * DIM + nt * 128 + wn;
            size_t r1 = r0 + (size_t)8 * DIM;
#pragma unroll
            for (int jn = 0; jn < 4; jn++) {
                int col = 8 * jn + 2 * qd;
                *(uint32_t*)&outh[r0 + col] = pkh2(acc[i][jn][0] * scl, acc[i][jn][1] * scl);
                *(uint32_t*)&outh[r1 + col] = pkh2(acc[i][jn][2] * scl, acc[i][jn][3] * scl);
            }
        }
    } else {
        // V: transpose through smem, then coalesced 16B stores of Vt rows.
        __syncthreads();
        __half* smT = (__half*)smem;           // [128 e][TST t]
#pragma unroll
        for (int i = 0; i < 4; i++) {
            int tl0 = wm + 16 * i + grp;
            int tl1 = tl0 + 8;
#pragma unroll
            for (int jn = 0; jn < 4; jn++) {
                int e0 = wn + 8 * jn + 2 * qd;
                smT[e0 * TST + tl0]       = __float2half(acc[i][jn][0]);
                smT[(e0 + 1) * TST + tl0] = __float2half(acc[i][jn][1]);
                smT[e0 * TST + tl1]       = __float2half(acc[i][jn][2]);
                smT[(e0 + 1) * TST + tl1] = __float2half(acc[i][jn][3]);
            }
        }
        __syncthreads();
        const int b  = (mt * 128) >> 8;
        const int t0 = (mt * 128) & (SEQT - 1);
        const size_t gb = ((size_t)(b * NJ + j) * DIM + nt * 128) * SEQT + t0;
#pragma unroll
        for (int l = 0; l < 8; l++) {
            int idx = tid + l * 256;
            int e   = idx >> 4;
            int q4  = idx & 15;
            uint4 v = *(uint4*)&smT[e * TST + q4 * 8];
            *(uint4*)&g_Vth[gb + (size_t)e * SEQT + q4 * 8] = v;
        }
    }
}

// ---------------------------------------------------------------------------
// Kernel 2: fp16 flash attention, ldmatrix, split-wait staging (Q/K group
// waits first; Vt group waited just before first PV), exp2 softmax.
// ---------------------------------------------------------------------------
#define AQ_ST 36
#define AV_ST 132
#define ATT_U (2 * SEQT * AQ_ST + HD * AV_ST)
#define ATT_SMEM (ATT_U * 4)

__global__ __launch_bounds__(512)
void attn_tc_kernel()
{
    extern __shared__ uint32_t smu[];
    const uint32_t sbase = (uint32_t)__cvta_generic_to_shared(smu);
    const uint32_t qs_b = sbase;
    const uint32_t ks_b = sbase + SEQT * AQ_ST * 4;
    const uint32_t vt_b = sbase + 2 * SEQT * AQ_ST * 4;

    const int bjh = blockIdx.x;
    const int h   = bjh & (NH - 1);
    const int bj  = bjh >> 3;
    const int tid  = threadIdx.x;
    const int wid  = tid >> 5;
    const int lane = tid & 31;
    const int grp  = lane >> 2;
    const int qd   = lane & 3;
    const int m0   = wid * 16;

    const int a_row = (lane & 15);
    const int a_k   = 4 * (lane >> 4);
    const int b_n   = (lane & 7) + 8 * (lane >> 4);
    const int b_k   = 4 * ((lane >> 3) & 1);

    const __half* qg = g_Qh + (size_t)bj * SEQT * DIM + h * HD;
    const __half* kg = g_Kh + (size_t)bj * SEQT * DIM + h * HD;
    const __half* vg = g_Vth + (size_t)bj * DIM * SEQT + (size_t)h * HD * SEQT;

    // group 0: Q + K
#pragma unroll
    for (int l = 0; l < 4; l++) {
        int idx = tid + l * 512;
        int row = idx >> 3;
        int q4  = idx & 7;
        cpasync16(qs_b + (row * AQ_ST + q4 * 4) * 4, qg + (size_t)row * DIM + q4 * 8);
        cpasync16(ks_b + (row * AQ_ST + q4 * 4) * 4, kg + (size_t)row * DIM + q4 * 8);
    }
    CP_COMMIT();
    // group 1: Vt
#pragma unroll
    for (int l = 0; l < 4; l++) {
        int idx = tid + l * 512;
        int d  = idx >> 5;
        int q4 = idx & 31;
        cpasync16(vt_b + (d * AV_ST + q4 * 4) * 4, vg + (size_t)d * SEQT + q4 * 8);
    }
    CP_COMMIT();
    CP_WAIT(1);          // Q + K ready; Vt may still be in flight
    __syncthreads();

    float oacc[8][4];
#pragma unroll
    for (int jn = 0; jn < 8; jn++)
#pragma unroll
        for (int c = 0; c < 4; c++) oacc[jn][c] = 0.0f;
    float mrow[2] = { -1e30f, -1e30f };
    float lrow[2] = { 0.0f, 0.0f };

    for (int ch = 0; ch < 4; ch++) {
        float sacc[8][4];
#pragma unroll
        for (int jn = 0; jn < 8; jn++)
#pragma unroll
            for (int c = 0; c < 4; c++) sacc[jn][c] = 0.0f;

#pragma unroll
        for (int kt = 0; kt < 4; kt++) {
            const int kp = kt * 8;
            uint32_t a0, a1, a2, a3;
            ldsm4(a0, a1, a2, a3,
                  qs_b + ((m0 + a_row) * AQ_ST + kp + a_k) * 4);
#pragma unroll
            for (int jp = 0; jp < 4; jp++) {
                uint32_t b00, b01, b10, b11;
                ldsm4(b00, b01, b10, b11,
                      ks_b + ((ch * 64 + 16 * jp + b_n) * AQ_ST + kp + b_k) * 4);
                mma_f16(sacc[2 * jp][0], sacc[2 * jp][1], sacc[2 * jp][2], sacc[2 * jp][3],
                        a0, a1, a2, a3, b00, b01);
                mma_f16(sacc[2 * jp + 1][0], sacc[2 * jp + 1][1],
                        sacc[2 * jp + 1][2], sacc[2 * jp + 1][3],
                        a0, a1, a2, a3, b10, b11);
            }
        }

        // online softmax in log2 domain (scores pre-scaled by log2(e))
#pragma unroll
        for (int r = 0; r < 2; r++) {
            float mx = -1e30f;
#pragma unroll
            for (int jn = 0; jn < 8; jn++) {
                mx = fmaxf(mx, sacc[jn][2 * r]);
                mx = fmaxf(mx, sacc[jn][2 * r + 1]);
            }
            mx = fmaxf(mx, __shfl_xor_sync(0xffffffffu, mx, 1));
            mx = fmaxf(mx, __shfl_xor_sync(0xffffffffu, mx, 2));
            float mnew = fmaxf(mrow[r], mx);
            float scale = exp2f(mrow[r] - mnew);
            mrow[r] = mnew;
            float ps = 0.0f;
#pragma unroll
            for (int jn = 0; jn < 8; jn++) {
                float p0 = exp2f(sacc[jn][2 * r] - mnew);
                float p1 = exp2f(sacc[jn][2 * r + 1] - mnew);
                sacc[jn][2 * r] = p0;
                sacc[jn][2 * r + 1] = p1;
                ps += p0 + p1;
                oacc[jn][2 * r] *= scale;
                oacc[jn][2 * r + 1] *= scale;
            }
            lrow[r] = lrow[r] * scale + ps;
        }

        if (ch == 0) {          // Vt needed from here on
            CP_WAIT(0);
            __syncthreads();
        }

#pragma unroll
        for (int kt = 0; kt < 4; kt++) {
            uint32_t a0 = pkh2(sacc[2 * kt][0], sacc[2 * kt][1]);
            uint32_t a1 = pkh2(sacc[2 * kt][2], sacc[2 * kt][3]);
            uint32_t a2 = pkh2(sacc[2 * kt + 1][0], sacc[2 * kt + 1][1]);
            uint32_t a3 = pkh2(sacc[2 * kt + 1][2], sacc[2 * kt + 1][3]);
            const int kp = ch * 32 + kt * 8;
#pragma unroll
            for (int jp = 0; jp < 4; jp++) {
                uint32_t b00, b01, b10, b11;
                ldsm4(b00, b01, b10, b11,
                      vt_b + ((16 * jp + b_n) * AV_ST + kp + b_k) * 4);
                mma_f16(oacc[2 * jp][0], oacc[2 * jp][1], oacc[2 * jp][2], oacc[2 * jp][3],
                        a0, a1, a2, a3, b00, b01);
                mma_f16(oacc[2 * jp + 1][0], oacc[2 * jp + 1][1],
                        oacc[2 * jp + 1][2], oacc[2 * jp + 1][3],
                        a0, a1, a2, a3, b10, b11);
            }
        }
    }

    float inv[2];
#pragma unroll
    for (int r = 0; r < 2; r++) {
        float lr = lrow[r];
        lr += __shfl_xor_sync(0xffffffffu, lr, 1);
        lr += __shfl_xor_sync(0xffffffffu, lr, 2);
        inv[r] = 1.0f / lr;
    }
    const size_t obase = (size_t)bj * SEQT * DIM + h * HD;
    __half* o0 = g_Oh + obase + (size_t)(m0 + grp) * DIM;
    __half* o1 = g_Oh + obase + (size_t)(m0 + grp + 8) * DIM;
#pragma unroll
    for (int jn = 0; jn < 8; jn++) {
        int col = 8 * jn + 2 * qd;
        *(uint32_t*)&o0[col] = pkh2(oacc[jn][0] * inv[0], oacc[jn][1] * inv[0]);
        *(uint32_t*)&o1[col] = pkh2(oacc[jn][2] * inv[1], oacc[jn][3] * inv[1]);
    }
}

// ---------------------------------------------------------------------------
// Kernel 3: output projection + bias, BK=64, 3-stage ring + ldmatrix
// (R14-verbatim).
// ---------------------------------------------------------------------------
#define PSAU 36
#define PABUF_U (128 * PSAU)
#define PSTG_U  (2 * PABUF_U)
#define PROJ_SMEM (3 * PSTG_U * 4)

__global__ __launch_bounds__(256, 2)
void proj_tc_kernel(const float* __restrict__ bo,
                    float* __restrict__ out)
{
    extern __shared__ uint32_t smem[];
    const uint32_t sbase = (uint32_t)__cvta_generic_to_shared(smem);

    const int nt = blockIdx.x;
    const int mt = blockIdx.y;

    const int tid  = threadIdx.x;
    const int wid  = tid >> 5;
    const int lane = tid & 31;
    const int wm   = (wid >> 2) * 64;
    const int wn   = (wid & 3) * 32;
    const int grp  = lane >> 2;
    const int qd   = lane & 3;

    const int a_row = (lane & 15);
    const int a_k   = 4 * (lane >> 4);
    const int b_n   = (lane & 7) + 8 * (lane >> 4);
    const int b_k   = 4 * ((lane >> 3) & 1);

    float acc[4][4][4];
#pragma unroll
    for (int i = 0; i < 4; i++)
#pragma unroll
        for (int jn = 0; jn < 4; jn++)
#pragma unroll
            for (int c = 0; c < 4; c++)
                acc[i][jn][c] = 0.0f;

    auto stage = [&](int kb, int bf) {
        uint32_t ab = sbase + bf * (PSTG_U * 4);
        uint32_t bb = ab + PABUF_U * 4;
#pragma unroll
        for (int l = 0; l < 4; l++) {
            int c   = tid + l * 256;
            int row = c >> 3;
            int cc  = c & 7;
            cpasync16(ab + row * (PSAU * 4) + cc * 16,
                      g_Oh + (size_t)(mt * 128 + row) * DIM + kb * 64 + cc * 8);
            cpasync16(bb + row * (PSAU * 4) + cc * 16,
                      g_Woh + (size_t)(nt * 128 + row) * DIM + kb * 64 + cc * 8);
        }
    };

    stage(0, 0);
    CP_COMMIT();
    stage(1, 1);
    CP_COMMIT();

    const int NKB = DIM / 64;
    for (int kb = 0; kb < NKB; kb++) {
        if (kb < NKB - 1) { CP_WAIT(1); } else { CP_WAIT(0); }
        __syncthreads();
        if (kb + 2 < NKB) {
            stage(kb + 2, (kb + 2) % 3);
            CP_COMMIT();
        }

        const uint32_t abase = sbase + (kb % 3) * (PSTG_U * 4);
        const uint32_t bbase = abase + PABUF_U * 4;

#pragma unroll
        for (int kk = 0; kk < 4; kk++) {
            const int kp = kk * 8;
            uint32_t a[4][4];
#pragma unroll
            for (int i = 0; i < 4; i++) {
                uint32_t addr = abase +
                    ((wm + 16 * i + a_row) * PSAU + kp + a_k) * 4;
                ldsm4(a[i][0], a[i][1], a[i][2], a[i][3], addr);
            }
            uint32_t b[4][2];
#pragma unroll
            for (int jp = 0; jp < 2; jp++) {
                uint32_t addr = bbase +
                    ((wn + 16 * jp + b_n) * PSAU + kp + b_k) * 4;
                ldsm4(b[2 * jp][0], b[2 * jp][1], b[2 * jp + 1][0], b[2 * jp + 1][1], addr);
            }
#pragma unroll
            for (int i = 0; i < 4; i++)
#pragma unroll
                for (int jn = 0; jn < 4; jn++)
                    mma_f16(acc[i][jn][0], acc[i][jn][1], acc[i][jn][2], acc[i][jn][3],
                            a[i][0], a[i][1], a[i][2], a[i][3],
                            b[jn][0], b[jn][1]);
        }
    }

#pragma unroll
    for (int i = 0; i < 4; i++) {
        int r = mt * 128 + wm + 16 * i + grp;
        int b = r / (NJ * SEQT);
        int rem = r - b * (NJ * SEQT);
        int jj = rem >> 8;
        int t  = rem & (SEQT - 1);
        size_t base0 = (((size_t)(b * SEQT + t) * NJ) + jj) * DIM + nt * 128 + wn;
        size_t base1 = base0 + (size_t)8 * NJ * DIM;
#pragma unroll
        for (int jn = 0; jn < 4; jn++) {
            int col = 8 * jn + 2 * qd;
            float2 bb = *(const float2*)(bo + nt * 128 + wn + col);
            *(float2*)&out[base0 + col] = make_float2(acc[i][jn][0] + bb.x,
                                                      acc[i][jn][1] + bb.y);
            *(float2*)&out[base1 + col] = make_float2(acc[i][jn][2] + bb.x,
                                                      acc[i][jn][3] + bb.y);
        }
    }
}

// ---------------------------------------------------------------------------
extern "C" void kernel_launch(void* const* d_in, const int* in_sizes, int n_in,
                              void* d_out, int out_size)
{
    const float* x  = (const float*)d_in[0];
    const float* Wq = (const float*)d_in[1];
    const float* Wk = (const float*)d_in[2];
    const float* Wv = (const float*)d_in[3];
    const float* Wo = (const float*)d_in[4];
    const float* bo = (const float*)d_in[5];
    float* out = (float*)d_out;

    // 0) fused pre-convert (one launch)
    cvt_fused_kernel<<<XB + WTB + WOB, 256>>>(
        (const float4*)x, Wq, Wk, Wv, (const float4*)Wo);

    // 1) QKV projection (BK=32, 3-stage cp.async + ldmatrix, smem V-transpose)
    cudaFuncSetAttribute(qkv_tc_kernel,
                         cudaFuncAttributeMaxDynamicSharedMemorySize, QKV_SMEM);
    dim3 g1(DIM / 128, (BSZ * SEQT) / 128, 3 * NJ);   // (4, 16, 72)
    qkv_tc_kernel<<<g1, 256, QKV_SMEM>>>();

    // 2) fp16 flash attention (split-wait staging, exp2 softmax)
    cudaFuncSetAttribute(attn_tc_kernel,
                         cudaFuncAttributeMaxDynamicSharedMemorySize, ATT_SMEM);
    attn_tc_kernel<<<BSZ * NJ * NH, 512, ATT_SMEM>>>();

    // 3) output projection + bias (BK=64, 3-stage + ldmatrix)
    cudaFuncSetAttribute(proj_tc_kernel,
                         cudaFuncAttributeMaxDynamicSharedMemorySize, PROJ_SMEM);
    dim3 g3(DIM / 128, (BSZ * SEQT * NJ) / 128);      // (4, 48)
    proj_tc_kernel<<<g3, 256, PROJ_SMEM>>>(bo, out);
}

// round 17
// speedup vs baseline: 1.1270x; 1.0485x over previous
#include <cuda_runtime.h>
#include <cuda_fp16.h>
#include <cstdint>

// Problem constants
#define BSZ 8
#define SEQT 256
#define NJ 24
#define DIM 512
#define NH 8
#define HD 64

#define QKV_ELEMS (BSZ * SEQT * NJ * DIM)  // 25,165,824
#define W_ELEMS   (NJ * DIM * DIM)         // 6,291,456

// fp16 operands / intermediates
__device__ __half g_Xh[QKV_ELEMS];       // x, layout [b][t][j][d]
__device__ __half g_Whq[W_ELEMS];        // W transposed: [j][n][k]
__device__ __half g_Whk[W_ELEMS];
__device__ __half g_Whv[W_ELEMS];
__device__ __half g_Woh[DIM * DIM];      // Wo [n][k]
__device__ __half g_Qh[QKV_ELEMS];       // Q pre-scaled by 0.125*log2(e), [b][j][t][e]
__device__ __half g_Kh[QKV_ELEMS];       // K, [b][j][t][e]
__device__ __half g_Vth[QKV_ELEMS];      // V transposed, [b][j][e][t]
__device__ __half g_Oh[QKV_ELEMS];       // attention out, [b][j][t][e]

__device__ __forceinline__ uint32_t pkh2(float x, float y) {
    __half2 h = __float22half2_rn(make_float2(x, y));
    return *(uint32_t*)&h;
}

__device__ __forceinline__ void mma_f16(
    float& c0, float& c1, float& c2, float& c3,
    uint32_t a0, uint32_t a1, uint32_t a2, uint32_t a3,
    uint32_t b0, uint32_t b1)
{
    asm volatile(
        "mma.sync.aligned.m16n8k16.row.col.f32.f16.f16.f32 "
        "{%0,%1,%2,%3}, {%4,%5,%6,%7}, {%8,%9}, {%0,%1,%2,%3};\n"
        : "+f"(c0), "+f"(c1), "+f"(c2), "+f"(c3)
        : "r"(a0), "r"(a1), "r"(a2), "r"(a3), "r"(b0), "r"(b1));
}

__device__ __forceinline__ void ldsm4(uint32_t& r0, uint32_t& r1,
                                      uint32_t& r2, uint32_t& r3, uint32_t addr)
{
    asm volatile("ldmatrix.sync.aligned.m8n8.x4.shared.b16 {%0,%1,%2,%3}, [%4];"
                 : "=r"(r0), "=r"(r1), "=r"(r2), "=r"(r3) : "r"(addr));
}

__device__ __forceinline__ void cpasync16(uint32_t dst, const void* src) {
    asm volatile("cp.async.cg.shared.global [%0], [%1], 16;\n"
                 :: "r"(dst), "l"(src));
}
#define CP_COMMIT() asm volatile("cp.async.commit_group;\n" ::: "memory")
#define CP_WAIT(N)  asm volatile("cp.async.wait_group %0;\n" :: "n"(N) : "memory")

// ---------------------------------------------------------------------------
// Fused pre-pass (R14-verbatim)
// ---------------------------------------------------------------------------
#define XB   (QKV_ELEMS / 4 / 256)           // 24576
#define WTB  (16 * 16 * 72)                  // 18432
#define WOB  (DIM * DIM / 4 / 256)           // 256

__global__ __launch_bounds__(256)
void cvt_fused_kernel(const float4* __restrict__ x,
                      const float* __restrict__ Wq,
                      const float* __restrict__ Wk,
                      const float* __restrict__ Wv,
                      const float4* __restrict__ Wo)
{
    __shared__ float tile[32][33];
    const int bid = blockIdx.x;
    const int tid = threadIdx.x;

    if (bid < XB) {
        int i = bid * 256 + tid;
        float4 v = x[i];
        ((uint2*)g_Xh)[i] = make_uint2(pkh2(v.x, v.y), pkh2(v.z, v.w));
    } else if (bid < XB + WTB) {
        int r = bid - XB;
        int bx = r & 15;
        int by = (r >> 4) & 15;
        int z  = r >> 8;
        int j  = z % NJ;
        int p  = z / NJ;
        const float* W = (p == 0) ? Wq : ((p == 1) ? Wk : Wv);
        __half* Wh     = (p == 0) ? g_Whq : ((p == 1) ? g_Whk : g_Whv);
        int n0 = bx * 32, k0 = by * 32;
        int tx = tid & 31, ty = tid >> 5;
        const size_t base = (size_t)j * DIM * DIM;
#pragma unroll
        for (int i = 0; i < 4; i++)
            tile[ty + 8 * i][tx] = W[base + (size_t)(k0 + ty + 8 * i) * DIM + n0 + tx];
        __syncthreads();
#pragma unroll
        for (int i = 0; i < 4; i++)
            Wh[base + (size_t)(n0 + ty + 8 * i) * DIM + k0 + tx] =
                __float2half(tile[tx][ty + 8 * i]);
    } else {
        int i = (bid - XB - WTB) * 256 + tid;
        float4 v = Wo[i];
        ((uint2*)g_Woh)[i] = make_uint2(pkh2(v.x, v.y), pkh2(v.z, v.w));
    }
}

// ---------------------------------------------------------------------------
// Kernel 1: per-joint Q/K/V projection (R16-verbatim).
// ---------------------------------------------------------------------------
#define QSAU 20
#define QABUF_U (128 * QSAU)
#define QSTG_U  (2 * QABUF_U)
#define QKV_SMEM (3 * QSTG_U * 4)
#define TST 136

__global__ __launch_bounds__(256, 2)
void qkv_tc_kernel()
{
    extern __shared__ uint32_t smem[];
    const uint32_t sbase = (uint32_t)__cvta_generic_to_shared(smem);

    const int nt = blockIdx.x;
    const int mt = blockIdx.y;
    const int z  = blockIdx.z;
    const int j  = z % NJ;
    const int p  = z / NJ;

    const __half* Wh = (p == 0) ? g_Whq : ((p == 1) ? g_Whk : g_Whv);

    const int tid  = threadIdx.x;
    const int wid  = tid >> 5;
    const int lane = tid & 31;
    const int wm   = (wid >> 2) * 64;
    const int wn   = (wid & 3) * 32;
    const int grp  = lane >> 2;
    const int qd   = lane & 3;

    const int a_row = (lane & 15);
    const int a_k   = 4 * (lane >> 4);
    const int b_n   = (lane & 7) + 8 * (lane >> 4);
    const int b_k   = 4 * ((lane >> 3) & 1);

    const size_t wbase = (size_t)j * DIM * DIM + (size_t)nt * 128 * DIM;

    float acc[4][4][4];
#pragma unroll
    for (int i = 0; i < 4; i++)
#pragma unroll
        for (int jn = 0; jn < 4; jn++)
#pragma unroll
            for (int c = 0; c < 4; c++)
                acc[i][jn][c] = 0.0f;

    auto stage = [&](int kb, int bf) {
        uint32_t ab = sbase + bf * (QSTG_U * 4);
        uint32_t bb = ab + QABUF_U * 4;
#pragma unroll
        for (int l = 0; l < 2; l++) {
            int c   = tid + l * 256;
            int row = c >> 2;
            int cc  = c & 3;
            cpasync16(ab + row * (QSAU * 4) + cc * 16,
                      g_Xh + ((size_t)(mt * 128 + row) * NJ + j) * DIM + kb * 32 + cc * 8);
            cpasync16(bb + row * (QSAU * 4) + cc * 16,
                      Wh + wbase + (size_t)row * DIM + kb * 32 + cc * 8);
        }
    };

    stage(0, 0);
    CP_COMMIT();
    stage(1, 1);
    CP_COMMIT();

    const int NKB = DIM / 32;
    for (int kb = 0; kb < NKB; kb++) {
        if (kb < NKB - 1) { CP_WAIT(1); } else { CP_WAIT(0); }
        __syncthreads();
        if (kb + 2 < NKB) {
            stage(kb + 2, (kb + 2) % 3);
            CP_COMMIT();
        }

        const uint32_t abase = sbase + (kb % 3) * (QSTG_U * 4);
        const uint32_t bbase = abase + QABUF_U * 4;

#pragma unroll
        for (int kk = 0; kk < 2; kk++) {
            const int kp = kk * 8;
            uint32_t a[4][4];
#pragma unroll
            for (int i = 0; i < 4; i++) {
                uint32_t addr = abase +
                    ((wm + 16 * i + a_row) * QSAU + kp + a_k) * 4;
                ldsm4(a[i][0], a[i][1], a[i][2], a[i][3], addr);
            }
            uint32_t b[4][2];
#pragma unroll
            for (int jp = 0; jp < 2; jp++) {
                uint32_t addr = bbase +
                    ((wn + 16 * jp + b_n) * QSAU + kp + b_k) * 4;
                ldsm4(b[2 * jp][0], b[2 * jp][1], b[2 * jp + 1][0], b[2 * jp + 1][1], addr);
            }
#pragma unroll
            for (int i = 0; i < 4; i++)
#pragma unroll
                for (int jn = 0; jn < 4; jn++)
                    mma_f16(acc[i][jn][0], acc[i][jn][1], acc[i][jn][2], acc[i][jn][3],
                            a[i][0], a[i][1], a[i][2], a[i][3],
                            b[jn][0], b[jn][1]);
        }
    }

    if (p < 2) {
        __half* outh = (p == 0) ? g_Qh : g_Kh;
        const float scl = (p == 0) ? (0.125f * 1.44269504f) : 1.0f;
#pragma unroll
        for (int i = 0; i < 4; i++) {
            int m = mt * 128 + wm + 16 * i + grp;
            int b = m >> 8;
            int t = m & (SEQT - 1);
            size_t r0 = (((size_t)(b * NJ + j) * SEQT) + t) * DIM + nt * 128 + wn;
            size_t r1 = r0 + (size_t)8 * DIM;
#pragma unroll
            for (int jn = 0; jn < 4; jn++) {
                int col = 8 * jn + 2 * qd;
                *(uint32_t*)&outh[r0 + col] = pkh2(acc[i][jn][0] * scl, acc[i][jn][1] * scl);
                *(uint32_t*)&outh[r1 + col] = pkh2(acc[i][jn][2] * scl, acc[i][jn][3] * scl);
            }
        }
    } else {
        __syncthreads();
        __half* smT = (__half*)smem;
#pragma unroll
        for (int i = 0; i < 4; i++) {
            int tl0 = wm + 16 * i + grp;
            int tl1 = tl0 + 8;
#pragma unroll
            for (int jn = 0; jn < 4; jn++) {
                int e0 = wn + 8 * jn + 2 * qd;
                smT[e0 * TST + tl0]       = __float2half(acc[i][jn][0]);
                smT[(e0 + 1) * TST + tl0] = __float2half(acc[i][jn][1]);
                smT[e0 * TST + tl1]       = __float2half(acc[i][jn][2]);
                smT[(e0 + 1) * TST + tl1] = __float2half(acc[i][jn][3]);
            }
        }
        __syncthreads();
        const int b  = (mt * 128) >> 8;
        const int t0 = (mt * 128) & (SEQT - 1);
        const size_t gb = ((size_t)(b * NJ + j) * DIM + nt * 128) * SEQT + t0;
#pragma unroll
        for (int l = 0; l < 8; l++) {
            int idx = tid + l * 256;
            int e   = idx >> 4;
            int q4  = idx & 15;
            uint4 v = *(uint4*)&smT[e * TST + q4 * 8];
            *(uint4*)&g_Vth[gb + (size_t)e * SEQT + q4 * 8] = v;
        }
    }
}

// ---------------------------------------------------------------------------
// Kernel 2: fp16 flash attention, q-split for 2 CTAs/SM.
// One block per (b,j,h,qh): 128 q-rows, 256 threads = 8 warps (16 rows each).
// K(256) + Vt full per block; hoisted Q fragments; split-wait; exp2 softmax.
// grid: BSZ*NJ*NH*2 = 3072.
// ---------------------------------------------------------------------------
#define AQ_ST 36
#define AV_ST 132
#define ATT_U ((128 + 256) * AQ_ST + HD * AV_ST)   // 22272 u32
#define ATT_SMEM (ATT_U * 4)                       // 89088 B

__global__ __launch_bounds__(256, 2)
void attn_tc_kernel()
{
    extern __shared__ uint32_t smu[];
    const uint32_t sbase = (uint32_t)__cvta_generic_to_shared(smu);
    const uint32_t qs_b = sbase;
    const uint32_t ks_b = sbase + 128 * AQ_ST * 4;
    const uint32_t vt_b = sbase + (128 + 256) * AQ_ST * 4;

    const int idx0 = blockIdx.x;
    const int qh   = idx0 & 1;           // query half
    const int bjh  = idx0 >> 1;
    const int h    = bjh & (NH - 1);
    const int bj   = bjh >> 3;
    const int tid  = threadIdx.x;
    const int wid  = tid >> 5;           // 0..7
    const int lane = tid & 31;
    const int grp  = lane >> 2;
    const int qd   = lane & 3;
    const int m0   = wid * 16;           // local q-row base (0..112)

    const int a_row = (lane & 15);
    const int a_k   = 4 * (lane >> 4);
    const int b_n   = (lane & 7) + 8 * (lane >> 4);
    const int b_k   = 4 * ((lane >> 3) & 1);

    const __half* qg = g_Qh + (size_t)bj * SEQT * DIM + h * HD + (size_t)qh * 128 * DIM;
    const __half* kg = g_Kh + (size_t)bj * SEQT * DIM + h * HD;
    const __half* vg = g_Vth + (size_t)bj * DIM * SEQT + (size_t)h * HD * SEQT;

    // group 0: Q (128 rows) + K (256 rows)
#pragma unroll
    for (int l = 0; l < 4; l++) {
        int idx = tid + l * 256;          // 0..1023
        int row = idx >> 3;               // 0..127
        int q4  = idx & 7;
        cpasync16(qs_b + (row * AQ_ST + q4 * 4) * 4, qg + (size_t)row * DIM + q4 * 8);
    }
#pragma unroll
    for (int l = 0; l < 8; l++) {
        int idx = tid + l * 256;          // 0..2047
        int row = idx >> 3;               // 0..255
        int q4  = idx & 7;
        cpasync16(ks_b + (row * AQ_ST + q4 * 4) * 4, kg + (size_t)row * DIM + q4 * 8);
    }
    CP_COMMIT();
    // group 1: Vt (64 x 256)
#pragma unroll
    for (int l = 0; l < 8; l++) {
        int idx = tid + l * 256;          // 0..2047
        int d  = idx >> 5;                // 0..63
        int q4 = idx & 31;
        cpasync16(vt_b + (d * AV_ST + q4 * 4) * 4, vg + (size_t)d * SEQT + q4 * 8);
    }
    CP_COMMIT();
    CP_WAIT(1);          // Q + K ready
    __syncthreads();

    // Hoist Q fragments (chunk-invariant)
    uint32_t qa[4][4];
#pragma unroll
    for (int kt = 0; kt < 4; kt++)
        ldsm4(qa[kt][0], qa[kt][1], qa[kt][2], qa[kt][3],
              qs_b + ((m0 + a_row) * AQ_ST + kt * 8 + a_k) * 4);

    float oacc[8][4];
#pragma unroll
    for (int jn = 0; jn < 8; jn++)
#pragma unroll
        for (int c = 0; c < 4; c++) oacc[jn][c] = 0.0f;
    float mrow[2] = { -1e30f, -1e30f };
    float lrow[2] = { 0.0f, 0.0f };

    for (int ch = 0; ch < 4; ch++) {
        float sacc[8][4];
#pragma unroll
        for (int jn = 0; jn < 8; jn++)
#pragma unroll
            for (int c = 0; c < 4; c++) sacc[jn][c] = 0.0f;

#pragma unroll
        for (int kt = 0; kt < 4; kt++) {
            const int kp = kt * 8;
#pragma unroll
            for (int jp = 0; jp < 4; jp++) {
                uint32_t b00, b01, b10, b11;
                ldsm4(b00, b01, b10, b11,
                      ks_b + ((ch * 64 + 16 * jp + b_n) * AQ_ST + kp + b_k) * 4);
                mma_f16(sacc[2 * jp][0], sacc[2 * jp][1], sacc[2 * jp][2], sacc[2 * jp][3],
                        qa[kt][0], qa[kt][1], qa[kt][2], qa[kt][3], b00, b01);
                mma_f16(sacc[2 * jp + 1][0], sacc[2 * jp + 1][1],
                        sacc[2 * jp + 1][2], sacc[2 * jp + 1][3],
                        qa[kt][0], qa[kt][1], qa[kt][2], qa[kt][3], b10, b11);
            }
        }

        // online softmax in log2 domain
#pragma unroll
        for (int r = 0; r < 2; r++) {
            float mx = -1e30f;
#pragma unroll
            for (int jn = 0; jn < 8; jn++) {
                mx = fmaxf(mx, sacc[jn][2 * r]);
                mx = fmaxf(mx, sacc[jn][2 * r + 1]);
            }
            mx = fmaxf(mx, __shfl_xor_sync(0xffffffffu, mx, 1));
            mx = fmaxf(mx, __shfl_xor_sync(0xffffffffu, mx, 2));
            float mnew = fmaxf(mrow[r], mx);
            float scale = exp2f(mrow[r] - mnew);
            mrow[r] = mnew;
            float ps = 0.0f;
#pragma unroll
            for (int jn = 0; jn < 8; jn++) {
                float p0 = exp2f(sacc[jn][2 * r] - mnew);
                float p1 = exp2f(sacc[jn][2 * r + 1] - mnew);
                sacc[jn][2 * r] = p0;
                sacc[jn][2 * r + 1] = p1;
                ps += p0 + p1;
                oacc[jn][2 * r] *= scale;
                oacc[jn][2 * r + 1] *= scale;
            }
            lrow[r] = lrow[r] * scale + ps;
        }

        if (ch == 0) {          // Vt needed from here on
            CP_WAIT(0);
            __syncthreads();
        }

#pragma unroll
        for (int kt = 0; kt < 4; kt++) {
            uint32_t a0 = pkh2(sacc[2 * kt][0], sacc[2 * kt][1]);
            uint32_t a1 = pkh2(sacc[2 * kt][2], sacc[2 * kt][3]);
            uint32_t a2 = pkh2(sacc[2 * kt + 1][0], sacc[2 * kt + 1][1]);
            uint32_t a3 = pkh2(sacc[2 * kt + 1][2], sacc[2 * kt + 1][3]);
            const int kp = ch * 32 + kt * 8;
#pragma unroll
            for (int jp = 0; jp < 4; jp++) {
                uint32_t b00, b01, b10, b11;
                ldsm4(b00, b01, b10, b11,
                      vt_b + ((16 * jp + b_n) * AV_ST + kp + b_k) * 4);
                mma_f16(oacc[2 * jp][0], oacc[2 * jp][1], oacc[2 * jp][2], oacc[2 * jp][3],
                        a0, a1, a2, a3, b00, b01);
                mma_f16(oacc[2 * jp + 1][0], oacc[2 * jp + 1][1],
                        oacc[2 * jp + 1][2], oacc[2 * jp + 1][3],
                        a0, a1, a2, a3, b10, b11);
            }
        }
    }

    float inv[2];
#pragma unroll
    for (int r = 0; r < 2; r++) {
        float lr = lrow[r];
        lr += __shfl_xor_sync(0xffffffffu, lr, 1);
        lr += __shfl_xor_sync(0xffffffffu, lr, 2);
        inv[r] = 1.0f / lr;
    }
    const size_t obase = (size_t)bj * SEQT * DIM + h * HD + (size_t)qh * 128 * DIM;
    __half* o0 = g_Oh + obase + (size_t)(m0 + grp) * DIM;
    __half* o1 = g_Oh + obase + (size_t)(m0 + grp + 8) * DIM;
#pragma unroll
    for (int jn = 0; jn < 8; jn++) {
        int col = 8 * jn + 2 * qd;
        *(uint32_t*)&o0[col] = pkh2(oacc[jn][0] * inv[0], oacc[jn][1] * inv[0]);
        *(uint32_t*)&o1[col] = pkh2(oacc[jn][2] * inv[1], oacc[jn][3] * inv[1]);
    }
}

// ---------------------------------------------------------------------------
// Kernel 3: output projection + bias (R16-verbatim).
// ---------------------------------------------------------------------------
#define PSAU 36
#define PABUF_U (128 * PSAU)
#define PSTG_U  (2 * PABUF_U)
#define PROJ_SMEM (3 * PSTG_U * 4)

__global__ __launch_bounds__(256, 2)
void proj_tc_kernel(const float* __restrict__ bo,
                    float* __restrict__ out)
{
    extern __shared__ uint32_t smem[];
    const uint32_t sbase = (uint32_t)__cvta_generic_to_shared(smem);

    const int nt = blockIdx.x;
    const int mt = blockIdx.y;

    const int tid  = threadIdx.x;
    const int wid  = tid >> 5;
    const int lane = tid & 31;
    const int wm   = (wid >> 2) * 64;
    const int wn   = (wid & 3) * 32;
    const int grp  = lane >> 2;
    const int qd   = lane & 3;

    const int a_row = (lane & 15);
    const int a_k   = 4 * (lane >> 4);
    const int b_n   = (lane & 7) + 8 * (lane >> 4);
    const int b_k   = 4 * ((lane >> 3) & 1);

    float acc[4][4][4];
#pragma unroll
    for (int i = 0; i < 4; i++)
#pragma unroll
        for (int jn = 0; jn < 4; jn++)
#pragma unroll
            for (int c = 0; c < 4; c++)
                acc[i][jn][c] = 0.0f;

    auto stage = [&](int kb, int bf) {
        uint32_t ab = sbase + bf * (PSTG_U * 4);
        uint32_t bb = ab + PABUF_U * 4;
#pragma unroll
        for (int l = 0; l < 4; l++) {
            int c   = tid + l * 256;
            int row = c >> 3;
            int cc  = c & 7;
            cpasync16(ab + row * (PSAU * 4) + cc * 16,
                      g_Oh + (size_t)(mt * 128 + row) * DIM + kb * 64 + cc * 8);
            cpasync16(bb + row * (PSAU * 4) + cc * 16,
                      g_Woh + (size_t)(nt * 128 + row) * DIM + kb * 64 + cc * 8);
        }
    };

    stage(0, 0);
    CP_COMMIT();
    stage(1, 1);
    CP_COMMIT();

    const int NKB = DIM / 64;
    for (int kb = 0; kb < NKB; kb++) {
        if (kb < NKB - 1) { CP_WAIT(1); } else { CP_WAIT(0); }
        __syncthreads();
        if (kb + 2 < NKB) {
            stage(kb + 2, (kb + 2) % 3);
            CP_COMMIT();
        }

        const uint32_t abase = sbase + (kb % 3) * (PSTG_U * 4);
        const uint32_t bbase = abase + PABUF_U * 4;

#pragma unroll
        for (int kk = 0; kk < 4; kk++) {
            const int kp = kk * 8;
            uint32_t a[4][4];
#pragma unroll
            for (int i = 0; i < 4; i++) {
                uint32_t addr = abase +
                    ((wm + 16 * i + a_row) * PSAU + kp + a_k) * 4;
                ldsm4(a[i][0], a[i][1], a[i][2], a[i][3], addr);
            }
            uint32_t b[4][2];
#pragma unroll
            for (int jp = 0; jp < 2; jp++) {
                uint32_t addr = bbase +
                    ((wn + 16 * jp + b_n) * PSAU + kp + b_k) * 4;
                ldsm4(b[2 * jp][0], b[2 * jp][1], b[2 * jp + 1][0], b[2 * jp + 1][1], addr);
            }
#pragma unroll
            for (int i = 0; i < 4; i++)
#pragma unroll
                for (int jn = 0; jn < 4; jn++)
                    mma_f16(acc[i][jn][0], acc[i][jn][1], acc[i][jn][2], acc[i][jn][3],
                            a[i][0], a[i][1], a[i][2], a[i][3],
                            b[jn][0], b[jn][1]);
        }
    }

#pragma unroll
    for (int i = 0; i < 4; i++) {
        int r = mt * 128 + wm + 16 * i + grp;
        int b = r / (NJ * SEQT);
        int rem = r - b * (NJ * SEQT);
        int jj = rem >> 8;
        int t  = rem & (SEQT - 1);
        size_t base0 = (((size_t)(b * SEQT + t) * NJ) + jj) * DIM + nt * 128 + wn;
        size_t base1 = base0 + (size_t)8 * NJ * DIM;
#pragma unroll
        for (int jn = 0; jn < 4; jn++) {
            int col = 8 * jn + 2 * qd;
            float2 bb = *(const float2*)(bo + nt * 128 + wn + col);
            *(float2*)&out[base0 + col] = make_float2(acc[i][jn][0] + bb.x,
                                                      acc[i][jn][1] + bb.y);
            *(float2*)&out[base1 + col] = make_float2(acc[i][jn][2] + bb.x,
                                                      acc[i][jn][3] + bb.y);
        }
    }
}

// ---------------------------------------------------------------------------
extern "C" void kernel_launch(void* const* d_in, const int* in_sizes, int n_in,
                              void* d_out, int out_size)
{
    const float* x  = (const float*)d_in[0];
    const float* Wq = (const float*)d_in[1];
    const float* Wk = (const float*)d_in[2];
    const float* Wv = (const float*)d_in[3];
    const float* Wo = (const float*)d_in[4];
    const float* bo = (const float*)d_in[5];
    float* out = (float*)d_out;

    // 0) fused pre-convert (one launch)
    cvt_fused_kernel<<<XB + WTB + WOB, 256>>>(
        (const float4*)x, Wq, Wk, Wv, (const float4*)Wo);

    // 1) QKV projection
    cudaFuncSetAttribute(qkv_tc_kernel,
                         cudaFuncAttributeMaxDynamicSharedMemorySize, QKV_SMEM);
    dim3 g1(DIM / 128, (BSZ * SEQT) / 128, 3 * NJ);   // (4, 16, 72)
    qkv_tc_kernel<<<g1, 256, QKV_SMEM>>>();

    // 2) fp16 flash attention (q-split, 2 CTAs/SM, hoisted Q frags)
    cudaFuncSetAttribute(attn_tc_kernel,
                         cudaFuncAttributeMaxDynamicSharedMemorySize, ATT_SMEM);
    attn_tc_kernel<<<BSZ * NJ * NH * 2, 256, ATT_SMEM>>>();

    // 3) output projection + bias
    cudaFuncSetAttribute(proj_tc_kernel,
                         cudaFuncAttributeMaxDynamicSharedMemorySize, PROJ_SMEM);
    dim3 g3(DIM / 128, (BSZ * SEQT * NJ) / 128);      // (4, 384)
    proj_tc_kernel<<<g3, 256, PROJ_SMEM>>>(bo, out);
}